// round 1
// baseline (speedup 1.0000x reference)
#include <cuda_runtime.h>

// Degree-3 SH constants (match reference)
#define SH_C0 0.28209479177387814f
#define SH_C1 0.4886025119029199f
#define SH_C2_0 1.0925484305920792f
#define SH_C2_1 (-1.0925484305920792f)
#define SH_C2_2 0.31539156525252005f
#define SH_C2_3 (-1.0925484305920792f)
#define SH_C2_4 0.5462742152960396f
#define SH_C3_0 (-0.5900435899266435f)
#define SH_C3_1 2.890611442640554f
#define SH_C3_2 (-0.4570457994644658f)
#define SH_C3_3 0.3731763325901154f
#define SH_C3_4 (-0.4570457994644658f)
#define SH_C3_5 1.445305721320277f
#define SH_C3_6 (-0.5900435899266435f)

__global__ void __launch_bounds__(256)
sh_gather_kernel(const float* __restrict__ means,
                 const float* __restrict__ fdc,
                 const float* __restrict__ frest,
                 const float* __restrict__ opac,
                 const float* __restrict__ c2w,
                 const int*   __restrict__ mask_idx,
                 const int*   __restrict__ step_p,
                 float* __restrict__ out,
                 int M)
{
    int i = blockIdx.x * blockDim.x + threadIdx.x;
    if (i >= M) return;

    const int j = mask_idx[i];

    // camera position = column 3 of (3,4) row-major
    const float cx = __ldg(&c2w[3]);
    const float cy = __ldg(&c2w[7]);
    const float cz = __ldg(&c2w[11]);

    const long long j3 = (long long)j * 3;
    float x = __ldg(&means[j3 + 0]) - cx;
    float y = __ldg(&means[j3 + 1]) - cy;
    float z = __ldg(&means[j3 + 2]) - cz;
    const float inv = rsqrtf(x * x + y * y + z * z);
    x *= inv; y *= inv; z *= inv;

    int n = __ldg(step_p) / 1000;
    if (n > 3) n = 3;

    // accumulate rgb = sum_b basis[b] * feat[b][c]
    float r = SH_C0 * __ldg(&fdc[j3 + 0]);
    float g = SH_C0 * __ldg(&fdc[j3 + 1]);
    float b = SH_C0 * __ldg(&fdc[j3 + 2]);

    const float* fr = frest + (long long)j * 45;  // (15,3) row-major, basis b -> fr[(b-1)*3 + c]

    if (n >= 1) {
        const float b1 = -SH_C1 * y;
        const float b2 =  SH_C1 * z;
        const float b3 = -SH_C1 * x;
        r = fmaf(b1, __ldg(&fr[0]), r); g = fmaf(b1, __ldg(&fr[1]), g); b = fmaf(b1, __ldg(&fr[2]), b);
        r = fmaf(b2, __ldg(&fr[3]), r); g = fmaf(b2, __ldg(&fr[4]), g); b = fmaf(b2, __ldg(&fr[5]), b);
        r = fmaf(b3, __ldg(&fr[6]), r); g = fmaf(b3, __ldg(&fr[7]), g); b = fmaf(b3, __ldg(&fr[8]), b);
    }
    if (n >= 2) {
        const float xx = x * x, yy = y * y, zz = z * z;
        const float xy = x * y, yz = y * z, xz = x * z;
        const float b4 = SH_C2_0 * xy;
        const float b5 = SH_C2_1 * yz;
        const float b6 = SH_C2_2 * (2.0f * zz - xx - yy);
        const float b7 = SH_C2_3 * xz;
        const float b8 = SH_C2_4 * (xx - yy);
        r = fmaf(b4, __ldg(&fr[ 9]), r); g = fmaf(b4, __ldg(&fr[10]), g); b = fmaf(b4, __ldg(&fr[11]), b);
        r = fmaf(b5, __ldg(&fr[12]), r); g = fmaf(b5, __ldg(&fr[13]), g); b = fmaf(b5, __ldg(&fr[14]), b);
        r = fmaf(b6, __ldg(&fr[15]), r); g = fmaf(b6, __ldg(&fr[16]), g); b = fmaf(b6, __ldg(&fr[17]), b);
        r = fmaf(b7, __ldg(&fr[18]), r); g = fmaf(b7, __ldg(&fr[19]), g); b = fmaf(b7, __ldg(&fr[20]), b);
        r = fmaf(b8, __ldg(&fr[21]), r); g = fmaf(b8, __ldg(&fr[22]), g); b = fmaf(b8, __ldg(&fr[23]), b);
        if (n >= 3) {
            const float b9  = SH_C3_0 * y * (3.0f * xx - yy);
            const float b10 = SH_C3_1 * xy * z;
            const float b11 = SH_C3_2 * y * (4.0f * zz - xx - yy);
            const float b12 = SH_C3_3 * z * (2.0f * zz - 3.0f * xx - 3.0f * yy);
            const float b13 = SH_C3_4 * x * (4.0f * zz - xx - yy);
            const float b14 = SH_C3_5 * z * (xx - yy);
            const float b15 = SH_C3_6 * x * (xx - 3.0f * yy);
            r = fmaf(b9,  __ldg(&fr[24]), r); g = fmaf(b9,  __ldg(&fr[25]), g); b = fmaf(b9,  __ldg(&fr[26]), b);
            r = fmaf(b10, __ldg(&fr[27]), r); g = fmaf(b10, __ldg(&fr[28]), g); b = fmaf(b10, __ldg(&fr[29]), b);
            r = fmaf(b11, __ldg(&fr[30]), r); g = fmaf(b11, __ldg(&fr[31]), g); b = fmaf(b11, __ldg(&fr[32]), b);
            r = fmaf(b12, __ldg(&fr[33]), r); g = fmaf(b12, __ldg(&fr[34]), g); b = fmaf(b12, __ldg(&fr[35]), b);
            r = fmaf(b13, __ldg(&fr[36]), r); g = fmaf(b13, __ldg(&fr[37]), g); b = fmaf(b13, __ldg(&fr[38]), b);
            r = fmaf(b14, __ldg(&fr[39]), r); g = fmaf(b14, __ldg(&fr[40]), g); b = fmaf(b14, __ldg(&fr[41]), b);
            r = fmaf(b15, __ldg(&fr[42]), r); g = fmaf(b15, __ldg(&fr[43]), g); b = fmaf(b15, __ldg(&fr[44]), b);
        }
    }

    // rgbs = max(rgb + 0.5, 0); layout: out[0:3M) rgbs row-major, out[3M:4M) opacities
    out[3 * i + 0] = fmaxf(r + 0.5f, 0.0f);
    out[3 * i + 1] = fmaxf(g + 0.5f, 0.0f);
    out[3 * i + 2] = fmaxf(b + 0.5f, 0.0f);
    out[(long long)3 * M + i] = __ldg(&opac[j]);
}

extern "C" void kernel_launch(void* const* d_in, const int* in_sizes, int n_in,
                              void* d_out, int out_size)
{
    const float* means = (const float*)d_in[0];
    const float* fdc   = (const float*)d_in[1];
    const float* frest = (const float*)d_in[2];
    const float* opac  = (const float*)d_in[3];
    const float* c2w   = (const float*)d_in[4];
    const int*   midx  = (const int*)  d_in[5];
    const int*   step  = (const int*)  d_in[6];
    float*       out   = (float*)d_out;

    const int M = in_sizes[5];
    const int threads = 256;
    const int blocks = (M + threads - 1) / threads;
    sh_gather_kernel<<<blocks, threads>>>(means, fdc, frest, opac, c2w, midx, step, out, M);
}